// round 11
// baseline (speedup 1.0000x reference)
#include <cuda_runtime.h>
#include <math_constants.h>

// ChamferDistance: x (8,8192,3) f32, y (8,8192,3) f32 -> scalar f32.
// FMA-pipe bound brute force with packed fma.rn.f32x2 (FFMA2).
//   d^2(q,r) = qq + (rr - 2*dot(q,r)); queries pre-scaled by -2; qq added in reduce.
//   min(sqrt(v+EPS)) == sqrt(min(v)+EPS) -> one sqrt per point at the end.
// R11: query-PAIR packing (lanes = 2 different queries), refs splatted in smem
// (32B/ref: rx,rx,ry,ry,rz,rz,rr,rr). Halves query register footprint
// (48 -> 24) at identical issue/fma counts per distance -> 8 blocks/SM
// (32 warps, was 24). Same proven loop structure as R9.

#define BATCH   8
#define NPTS    8192
#define RSPLIT  32
#define TPB     128
#define U       8                              // queries per thread (4 packed pairs)
#define NP      (U / 2)                        // 4 pairs
#define QPB     (TPB * U)                      // 1024 queries per block
#define QBLK    (BATCH * NPTS / QPB)           // 64
#define TR      128                            // reference points per smem tile
#define RCHUNK  (NPTS / RSPLIT)                // 256
#define NTILES  (RCHUNK / TR)                  // 2
#define EPS_F   1e-10f

__device__ float g_minpart[2][RSPLIT][BATCH * NPTS];
__device__ float g_partial[128];

__device__ __forceinline__ unsigned long long f2_fma(unsigned long long a, unsigned long long b, unsigned long long c) {
    unsigned long long d;
    asm("fma.rn.f32x2 %0, %1, %2, %3;" : "=l"(d) : "l"(a), "l"(b), "l"(c));
    return d;
}
__device__ __forceinline__ unsigned long long f2_pack(float a, float b) {
    unsigned long long r;
    asm("mov.b64 %0, {%1, %2};" : "=l"(r) : "f"(a), "f"(b));
    return r;
}
__device__ __forceinline__ void f2_unpack(unsigned long long v, float& lo, float& hi) {
    asm("mov.b64 {%0, %1}, %2;" : "=f"(lo), "=f"(hi) : "l"(v));
}

__global__ __launch_bounds__(TPB, 8)
void chamfer_pass_kernel(const float* __restrict__ x, const float* __restrict__ y) {
    const int dir = blockIdx.z;
    const float* __restrict__ Q = dir ? y : x;   // query side
    const float* __restrict__ R = dir ? x : y;   // reference side

    const int qbase = blockIdx.x * QPB;          // within one batch (8 blocks/batch)
    const int b     = qbase / NPTS;
    const int r0    = blockIdx.y * RCHUNK;
    const int t     = threadIdx.x;

    // Splatted ref tile: ref j occupies sm[8j..8j+7] = rx,rx,ry,ry,rz,rz,rr,rr.
    __shared__ float sm[TR * 8];

    // 4 query pairs per thread; pair p = queries (qbase + p*256 + 2t, +1).
    unsigned long long qx2[NP], qy2[NP], qz2[NP];  // packed (q0,q1), pre-scaled by -2
    float minv[U];
#pragma unroll
    for (int p = 0; p < NP; p++) {
        const float* p0 = Q + (size_t)(qbase + p * 256 + 2 * t) * 3;
        qx2[p] = f2_pack(p0[0] * -2.0f, p0[3] * -2.0f);
        qy2[p] = f2_pack(p0[1] * -2.0f, p0[4] * -2.0f);
        qz2[p] = f2_pack(p0[2] * -2.0f, p0[5] * -2.0f);
        minv[2 * p]     = CUDART_INF_F;
        minv[2 * p + 1] = CUDART_INF_F;
    }

    const float* __restrict__ Rb = R + (size_t)b * NPTS * 3;

#pragma unroll 1
    for (int tile = 0; tile < NTILES; tile++) {
        __syncthreads();
        {
            const float* rp = Rb + (size_t)(r0 + tile * TR + t) * 3;   // TR == TPB
            float rx = rp[0], ry = rp[1], rz = rp[2];
            float rr = rx * rx + ry * ry + rz * rz;
            float4* d = reinterpret_cast<float4*>(&sm[t * 8]);
            d[0] = make_float4(rx, rx, ry, ry);
            d[1] = make_float4(rz, rz, rr, rr);
        }
        __syncthreads();

#pragma unroll 8
        for (int j = 0; j < TR; j++) {
            // Two broadcast LDS.128 -> (rx,rx),(ry,ry) and (rz,rz),(rr,rr)
            ulonglong2 A  = *reinterpret_cast<const ulonglong2*>(&sm[8 * j]);
            ulonglong2 Bv = *reinterpret_cast<const ulonglong2*>(&sm[8 * j + 4]);
#pragma unroll
            for (int p = 0; p < NP; p++) {
                unsigned long long acc = f2_fma(qx2[p], A.x, Bv.y);  // rr - 2 qx rx
                acc = f2_fma(qy2[p], A.y, acc);
                acc = f2_fma(qz2[p], Bv.x, acc);                     // rr - 2 dot (2 queries)
                float lo, hi;
                f2_unpack(acc, lo, hi);
                minv[2 * p]     = fminf(minv[2 * p], lo);
                minv[2 * p + 1] = fminf(minv[2 * p + 1], hi);
            }
        }
    }

    // Store: pair p -> queries qbase + p*256 + 2t (+1): one float2 per pair.
#pragma unroll
    for (int p = 0; p < NP; p++) {
        float2 v = make_float2(minv[2 * p], minv[2 * p + 1]);
        *reinterpret_cast<float2*>(&g_minpart[dir][blockIdx.y][qbase + p * 256 + 2 * t]) = v;
    }
}

// 128 blocks: dir(2) x batch(8) x chunk(8); each covers 1024 queries.
// Adds the deferred qq term before the sqrt.
__global__ __launch_bounds__(256)
void chamfer_reduce_kernel(const float* __restrict__ x, const float* __restrict__ y) {
    const int dir   = blockIdx.x >> 6;
    const int b     = (blockIdx.x >> 3) & 7;
    const int chunk = blockIdx.x & 7;
    const int t     = threadIdx.x;
    const float* __restrict__ Qside = dir ? y : x;

    float s = 0.0f;
#pragma unroll
    for (int k = 0; k < 4; k++) {
        const int q = b * NPTS + chunk * 1024 + k * 256 + t;
        float v = g_minpart[dir][0][q];
#pragma unroll
        for (int r = 1; r < RSPLIT; r++) v = fminf(v, g_minpart[dir][r][q]);
        const float* p = Qside + (size_t)q * 3;
        float qq = p[0] * p[0] + p[1] * p[1] + p[2] * p[2];
        s += sqrtf(v + qq + EPS_F);
    }

    __shared__ float red[256];
    red[t] = s;
    __syncthreads();
    for (int o = 128; o > 0; o >>= 1) {
        if (t < o) red[t] += red[t + o];
        __syncthreads();
    }
    if (t == 0) g_partial[blockIdx.x] = red[0];
}

// One block, 128 threads: parallel load of the 128 partials, smem tree.
__global__ __launch_bounds__(128)
void chamfer_final_kernel(float* __restrict__ out) {
    const int t = threadIdx.x;
    __shared__ float red[128];
    red[t] = g_partial[t];
    __syncthreads();
    if (t < 16) {
        float s = 0.0f;
#pragma unroll
        for (int c = 0; c < 8; c++) s += red[t * 8 + c];
        red[t] = s;
    }
    __syncthreads();
    if (t == 0) {
        float s = 0.0f;
#pragma unroll
        for (int b = 0; b < BATCH; b++)
            s += fmaxf(red[b], red[8 + b]) * (1.0f / (float)NPTS);
        *out = s;
    }
}

extern "C" void kernel_launch(void* const* d_in, const int* in_sizes, int n_in,
                              void* d_out, int out_size) {
    const float* x = (const float*)d_in[0];
    const float* y = (const float*)d_in[1];
    float* out = (float*)d_out;

    dim3 grid(QBLK, RSPLIT, 2);                  // 64 x 32 x 2 = 4096 blocks
    chamfer_pass_kernel<<<grid, TPB>>>(x, y);
    chamfer_reduce_kernel<<<128, 256>>>(x, y);
    chamfer_final_kernel<<<1, 128>>>(out);
}

// round 12
// speedup vs baseline: 1.1356x; 1.1356x over previous
#include <cuda_runtime.h>
#include <math_constants.h>

// ChamferDistance: x (8,8192,3) f32, y (8,8192,3) f32 -> scalar f32.
// FMA-pipe bound brute force with packed fma.rn.f32x2 (FFMA2).
//   d^2(q,r) = qq + (rr - 2*dot(q,r)); queries pre-scaled by -2; qq added in reduce.
//   min(sqrt(v+EPS)) == sqrt(min(v)+EPS) -> one sqrt per point at the end.
// R12: R9 champion loop (U=8, lanes = 2 refs, 2.63 issues/distance) with the
// register budget trimmed to fit 7 blocks/SM (<=73 regs via launch_bounds(128,7),
// dir/batch folded into blockIdx.z, store math deferred past the hot loop).

#define BATCH   8
#define NPTS    8192
#define RSPLIT  32
#define TPB     128
#define U       8                              // queries per thread
#define QPB     (TPB * U)                      // 1024 queries per block
#define QBLK    (NPTS / QPB)                   // 8 blocks per batch per dir
#define TR      128                            // reference points per smem tile
#define RCHUNK  (NPTS / RSPLIT)                // 256
#define NTILES  (RCHUNK / TR)                  // 2
#define EPS_F   1e-10f

__device__ float g_minpart[2][RSPLIT][BATCH * NPTS];
__device__ float g_partial[128];

__device__ __forceinline__ unsigned long long f2_fma(unsigned long long a, unsigned long long b, unsigned long long c) {
    unsigned long long d;
    asm("fma.rn.f32x2 %0, %1, %2, %3;" : "=l"(d) : "l"(a), "l"(b), "l"(c));
    return d;
}
__device__ __forceinline__ unsigned long long f2_pack(float a, float b) {
    unsigned long long r;
    asm("mov.b64 %0, {%1, %2};" : "=l"(r) : "f"(a), "f"(b));
    return r;
}
__device__ __forceinline__ void f2_unpack(unsigned long long v, float& lo, float& hi) {
    asm("mov.b64 {%0, %1}, %2;" : "=f"(lo), "=f"(hi) : "l"(v));
}

// grid: (QBLK=8, RSPLIT=32, 16)  where z = dir*8 + b
__global__ __launch_bounds__(TPB, 7)
void chamfer_pass_kernel(const float* __restrict__ x, const float* __restrict__ y) {
    const int dir = blockIdx.z >> 3;
    const int b   = blockIdx.z & 7;
    const float* __restrict__ Q = dir ? y : x;   // query side
    const float* __restrict__ R = dir ? x : y;   // reference side

    const int t = threadIdx.x;

    // Pair-interleaved tile: for ref pair j (points 2j, 2j+1):
    //   sm[8j+0..1]=x pair, [8j+2..3]=y pair, [8j+4..5]=z pair, [8j+6..7]=rr pair
    __shared__ float sm[TR * 4];

    float minv[U];
    unsigned long long qx2[U], qy2[U], qz2[U];   // query coords pre-scaled by -2, splatted
    {
        const float* qp = Q + ((size_t)b * NPTS + blockIdx.x * QPB + t) * 3;
#pragma unroll
        for (int u = 0; u < U; u++) {
            float a = qp[0] * -2.0f, c = qp[1] * -2.0f, e = qp[2] * -2.0f;
            qx2[u] = f2_pack(a, a);
            qy2[u] = f2_pack(c, c);
            qz2[u] = f2_pack(e, e);
            minv[u] = CUDART_INF_F;
            qp += TPB * 3;
        }
    }

    // Ref tile base pointer for this chunk (advances by TR*3 per tile).
    const float* rp0 = R + ((size_t)b * NPTS + blockIdx.y * RCHUNK + t) * 3;

#pragma unroll 1
    for (int tile = 0; tile < NTILES; tile++) {
        __syncthreads();
        {
            const float* rp = rp0 + tile * (TR * 3);   // TR == TPB: one point per thread
            float rx = rp[0], ry = rp[1], rz = rp[2];
            const int jj = (t >> 1) * 8 + (t & 1);
            sm[jj + 0] = rx;
            sm[jj + 2] = ry;
            sm[jj + 4] = rz;
            sm[jj + 6] = rx * rx + ry * ry + rz * rz;
        }
        __syncthreads();

#pragma unroll 4
        for (int j = 0; j < TR / 2; j++) {
            // Two LDS.128 -> four pre-packed f32x2 operands (broadcast, conflict-free),
            // each pair reused by 8 queries.
            ulonglong2 A  = *reinterpret_cast<const ulonglong2*>(&sm[8 * j]);      // {x-pair, y-pair}
            ulonglong2 Bv = *reinterpret_cast<const ulonglong2*>(&sm[8 * j + 4]);  // {z-pair, rr-pair}
#pragma unroll
            for (int u = 0; u < U; u++) {
                unsigned long long acc = f2_fma(qx2[u], A.x, Bv.y);  // rr - 2 qx rx
                acc = f2_fma(qy2[u], A.y, acc);
                acc = f2_fma(qz2[u], Bv.x, acc);                     // rr - 2 dot (packed x2)
                float lo, hi;
                f2_unpack(acc, lo, hi);
                minv[u] = fminf(minv[u], fminf(lo, hi));
            }
        }
    }

    // Store (address math intentionally after the hot loop; regs reusable here).
    float* outp = &g_minpart[dir][blockIdx.y][b * NPTS + blockIdx.x * QPB + t];
#pragma unroll
    for (int u = 0; u < U; u++) {
        outp[u * TPB] = minv[u];
    }
}

// 128 blocks: dir(2) x batch(8) x chunk(8); each covers 1024 queries.
// Adds the deferred qq term before the sqrt.
__global__ __launch_bounds__(256)
void chamfer_reduce_kernel(const float* __restrict__ x, const float* __restrict__ y) {
    const int dir   = blockIdx.x >> 6;
    const int b     = (blockIdx.x >> 3) & 7;
    const int chunk = blockIdx.x & 7;
    const int t     = threadIdx.x;
    const float* __restrict__ Qside = dir ? y : x;

    float s = 0.0f;
#pragma unroll
    for (int k = 0; k < 4; k++) {
        const int q = b * NPTS + chunk * 1024 + k * 256 + t;
        float v = g_minpart[dir][0][q];
#pragma unroll
        for (int r = 1; r < RSPLIT; r++) v = fminf(v, g_minpart[dir][r][q]);
        const float* p = Qside + (size_t)q * 3;
        float qq = p[0] * p[0] + p[1] * p[1] + p[2] * p[2];
        s += sqrtf(v + qq + EPS_F);
    }

    __shared__ float red[256];
    red[t] = s;
    __syncthreads();
    for (int o = 128; o > 0; o >>= 1) {
        if (t < o) red[t] += red[t + o];
        __syncthreads();
    }
    if (t == 0) g_partial[blockIdx.x] = red[0];
}

// One block, 128 threads: parallel load of the 128 partials, smem tree.
__global__ __launch_bounds__(128)
void chamfer_final_kernel(float* __restrict__ out) {
    const int t = threadIdx.x;
    __shared__ float red[128];
    red[t] = g_partial[t];
    __syncthreads();
    if (t < 16) {
        float s = 0.0f;
#pragma unroll
        for (int c = 0; c < 8; c++) s += red[t * 8 + c];
        red[t] = s;
    }
    __syncthreads();
    if (t == 0) {
        float s = 0.0f;
#pragma unroll
        for (int b = 0; b < BATCH; b++)
            s += fmaxf(red[b], red[8 + b]) * (1.0f / (float)NPTS);
        *out = s;
    }
}

extern "C" void kernel_launch(void* const* d_in, const int* in_sizes, int n_in,
                              void* d_out, int out_size) {
    const float* x = (const float*)d_in[0];
    const float* y = (const float*)d_in[1];
    float* out = (float*)d_out;

    dim3 grid(QBLK, RSPLIT, 16);                 // 8 x 32 x 16 = 4096 blocks
    chamfer_pass_kernel<<<grid, TPB>>>(x, y);
    chamfer_reduce_kernel<<<128, 256>>>(x, y);
    chamfer_final_kernel<<<1, 128>>>(out);
}